// round 10
// baseline (speedup 1.0000x reference)
#include <cuda_runtime.h>
#include <cuda_fp16.h>
#include <math.h>

#define Nn 8192
#define Dd 64
#define NCHUNK 128             // row chunks in v-pass
#define VROWS (Nn / NCHUNK)    // 64 rows per chunk
#define VCOLS 1024             // cols per tile (128 threads * 8)
#define NTILE (Nn / VCOLS)     // 8

#define R_ROWS 6656            // rows of C pinned in L2 (109 MB); rest streams
#define R_CHUNK (R_ROWS / VROWS)   // 104 resident chunks in v-pass
#define R_UBLK (R_ROWS / 8)        // 832 resident blocks in u-pass

#define LOG_AB (-9.010913347f)   // -ln(8192)
#define LOG2E  (1.4426950408889634f)
#define LN2    (0.6931471805599453f)
#define BIAS   (12.0f)

// ---------------- device scratch ----------
__device__ __half d_C[(size_t)Nn * Nn];    // C (fp16) then rescaled a' = C*alpha+12
__device__ float d_x2[Nn], d_y2[Nn];
__device__ float d_u[Nn], d_v[Nn];
__device__ float d_spart[NCHUNK][Nn];
__device__ float d_Tpart[NCHUNK][Nn];
__device__ float d_rj[Nn];
__device__ unsigned int d_cmax_bits;
__device__ float d_alpha;                  // negS*LOG2E  (negative)
__device__ float d_invAlpha;               // 1/alpha

__device__ __forceinline__ __half2 h2exp2_fast(__half2 x) {
    unsigned xi = *reinterpret_cast<unsigned*>(&x);
    unsigned ri;
    asm("ex2.approx.f16x2 %0, %1;" : "=r"(ri) : "r"(xi));
    return *reinterpret_cast<__half2*>(&ri);
}

__device__ __forceinline__ unsigned long long pol_last() {
    unsigned long long p;
    asm("createpolicy.fractional.L2::evict_last.b64 %0, 1.0;" : "=l"(p));
    return p;
}
__device__ __forceinline__ unsigned long long pol_first() {
    unsigned long long p;
    asm("createpolicy.fractional.L2::evict_first.b64 %0, 1.0;" : "=l"(p));
    return p;
}

// 128-bit load with L2 cache-hint policy
__device__ __forceinline__ uint4 ldgC_pol(const __half* p, unsigned long long pol) {
    uint4 r;
    asm("ld.global.nc.L2::cache_hint.v4.u32 {%0,%1,%2,%3}, [%4], %5;"
        : "=r"(r.x), "=r"(r.y), "=r"(r.z), "=r"(r.w) : "l"(p), "l"(pol));
    return r;
}

// ---------------- row norms ----------------
__global__ void norms_kernel(const float* __restrict__ XP,
                             const float* __restrict__ XQ) {
    int gwarp = (blockIdx.x * blockDim.x + threadIdx.x) >> 5;
    int lane = threadIdx.x & 31;
    const float* src;
    float* dst;
    int row;
    if (gwarp < Nn) { src = XP; dst = d_x2; row = gwarp; }
    else            { src = XQ; dst = d_y2; row = gwarp - Nn; }
    const float* r = src + (size_t)row * Dd;
    float a = r[lane];
    float b = r[lane + 32];
    float s = a * a + b * b;
    #pragma unroll
    for (int o = 16; o; o >>= 1) s += __shfl_xor_sync(0xffffffffu, s, o);
    if (lane == 0) dst[row] = s;
}

__global__ void init_kernel() {
    int j = blockIdx.x * blockDim.x + threadIdx.x;
    d_u[j] = 0.0f;
    d_v[j] = 0.0f;
    if (j == 0) d_cmax_bits = 0u;
}

// ---------------- C = max(x2 + y2 - 2 XP@XQ^T, 0) -> fp16, track fp32 max --
__global__ void gemmC_kernel(const float* __restrict__ XP,
                             const float* __restrict__ XQ) {
    __shared__ float As[Dd][64 + 4];
    __shared__ float Bs[Dd][64 + 4];
    int tid = threadIdx.x;             // 256 threads
    int m0 = blockIdx.y * 64;
    int n0 = blockIdx.x * 64;

    #pragma unroll
    for (int p = 0; p < 4; ++p) {
        int f = p * 256 + tid;
        int row = f >> 4;
        int c4 = f & 15;
        float4 a = *(const float4*)(XP + (size_t)(m0 + row) * Dd + c4 * 4);
        As[c4 * 4 + 0][row] = a.x; As[c4 * 4 + 1][row] = a.y;
        As[c4 * 4 + 2][row] = a.z; As[c4 * 4 + 3][row] = a.w;
        float4 b = *(const float4*)(XQ + (size_t)(n0 + row) * Dd + c4 * 4);
        Bs[c4 * 4 + 0][row] = b.x; Bs[c4 * 4 + 1][row] = b.y;
        Bs[c4 * 4 + 2][row] = b.z; Bs[c4 * 4 + 3][row] = b.w;
    }
    __syncthreads();

    int tx = tid & 15, ty = tid >> 4;
    float acc[4][4] = {};
    #pragma unroll
    for (int k = 0; k < Dd; ++k) {
        float4 a4 = *(const float4*)&As[k][ty * 4];
        float4 b4 = *(const float4*)&Bs[k][tx * 4];
        float a[4] = {a4.x, a4.y, a4.z, a4.w};
        float b[4] = {b4.x, b4.y, b4.z, b4.w};
        #pragma unroll
        for (int i = 0; i < 4; ++i)
            #pragma unroll
            for (int j = 0; j < 4; ++j)
                acc[i][j] = fmaf(a[i], b[j], acc[i][j]);
    }

    float cmaxl = 0.0f;
    #pragma unroll
    for (int i = 0; i < 4; ++i) {
        int m = m0 + ty * 4 + i;
        float xm = d_x2[m];
        float o[4];
        #pragma unroll
        for (int j = 0; j < 4; ++j) {
            int nj = n0 + tx * 4 + j;
            float c = fmaxf(xm + d_y2[nj] - 2.0f * acc[i][j], 0.0f);
            o[j] = c;
            cmaxl = fmaxf(cmaxl, c);
        }
        __half2* dst = (__half2*)(d_C + (size_t)m * Nn + n0 + tx * 4);
        dst[0] = __floats2half2_rn(o[0], o[1]);
        dst[1] = __floats2half2_rn(o[2], o[3]);
    }
    #pragma unroll
    for (int o = 16; o; o >>= 1)
        cmaxl = fmaxf(cmaxl, __shfl_xor_sync(0xffffffffu, cmaxl, o));
    if ((tid & 31) == 0)
        atomicMax(&d_cmax_bits, __float_as_uint(cmaxl));  // nonneg floats: bit order == value order
}

__global__ void scale_kernel() {
    float cmax = __uint_as_float(d_cmax_bits);
    float negS = -1.0f / (0.05f * cmax);
    float alpha = negS * LOG2E;
    d_alpha = alpha;
    d_invAlpha = 1.0f / alpha;
}

// a' = C*alpha + 12, in place (fp16); pre-warm pinned region with evict_last
__global__ void rescale_kernel() {
    float alpha = d_alpha;
    size_t idx = ((size_t)blockIdx.x * 256 + threadIdx.x) * 8;
    uint4 raw = *(uint4*)(d_C + idx);
    __half2* hp = (__half2*)&raw;
    #pragma unroll
    for (int k = 0; k < 4; ++k) {
        float2 f = __half22float2(hp[k]);
        hp[k] = __floats2half2_rn(fmaf(f.x, alpha, BIAS), fmaf(f.y, alpha, BIAS));
    }
    if (idx < (size_t)R_ROWS * Nn) {
        unsigned long long pol = pol_last();
        asm volatile("st.global.L2::cache_hint.v4.u32 [%0], {%1,%2,%3,%4}, %5;"
                     :: "l"(d_C + idx), "r"(raw.x), "r"(raw.y), "r"(raw.z), "r"(raw.w),
                        "l"(pol));
    } else {
        *(uint4*)(d_C + idx) = raw;
    }
}

// ---------------- u-pass body ----------------------------------------------
__device__ __forceinline__ float upass_row(const __half* Crow, const __half2* vs2,
                                           int lane, unsigned long long pol) {
    float2 f0 = make_float2(0.f, 0.f), f1 = f0, f2 = f0, f3 = f0;
    #pragma unroll
    for (int blk = 0; blk < 4; ++blk) {
        __half2 h0 = __float2half2_rn(0.f), h1 = h0, h2 = h0, h3 = h0;
        #pragma unroll
        for (int it = 0; it < 8; ++it) {
            int j = (blk * 8 + it) * 256 + lane * 8;
            uint4 raw = ldgC_pol(Crow + j, pol);
            uint4 vr = *(const uint4*)&vs2[j >> 1];
            const __half2* a = (const __half2*)&raw;
            const __half2* v = (const __half2*)&vr;
            h0 = __hadd2(h0, h2exp2_fast(__hadd2(a[0], v[0])));
            h1 = __hadd2(h1, h2exp2_fast(__hadd2(a[1], v[1])));
            h2 = __hadd2(h2, h2exp2_fast(__hadd2(a[2], v[2])));
            h3 = __hadd2(h3, h2exp2_fast(__hadd2(a[3], v[3])));
        }
        float2 g;
        g = __half22float2(h0); f0.x += g.x; f0.y += g.y;
        g = __half22float2(h1); f1.x += g.x; f1.y += g.y;
        g = __half22float2(h2); f2.x += g.x; f2.y += g.y;
        g = __half22float2(h3); f3.x += g.x; f3.y += g.y;
    }
    return ((f0.x + f0.y) + (f1.x + f1.y)) + ((f2.x + f2.y) + (f3.x + f3.y));
}

// u_new = up - rc*ln2 - ln( sum_j 2^(a' + v_j*log2e) )
__global__ void upass_kernel() {
    __shared__ __half2 vs2[Nn / 2];    // 8 KB: v_j*LOG2E as half2
    int tid = threadIdx.x;             // 256
    #pragma unroll
    for (int p = 0; p < 8; ++p) {
        int idx = p * 256 + tid;       // float4 index
        float4 f = *(const float4*)&d_v[idx * 4];
        vs2[idx * 2]     = __floats2half2_rn(f.x * LOG2E, f.y * LOG2E);
        vs2[idx * 2 + 1] = __floats2half2_rn(f.z * LOG2E, f.w * LOG2E);
    }
    __syncthreads();

    int warp = tid >> 5, lane = tid & 31;
    int row = blockIdx.x * 8 + warp;
    float up = d_u[row];
    const __half* Crow = d_C + (size_t)row * Nn;

    unsigned long long pol = (blockIdx.x < R_UBLK) ? pol_last() : pol_first();
    float s = upass_row(Crow, vs2, lane, pol);
    #pragma unroll
    for (int o = 16; o; o >>= 1) s += __shfl_xor_sync(0xffffffffu, s, o);
    if (lane == 0) {
        float rc = (up - LOG_AB) * LOG2E - BIAS;
        d_u[row] = up - rc * LN2 - __logf(s);
    }
}

// ---------------- v-pass body ----------------------------------------------
template <bool FINAL>
__device__ __forceinline__ void vpass_body(const __half* Cp, const __half2* us2,
                                           float2* f, float2* t,
                                           unsigned long long pol) {
    #pragma unroll
    for (int blk = 0; blk < VROWS / 8; ++blk) {
        __half2 h0 = __float2half2_rn(0.f), h1 = h0, h2 = h0, h3 = h0;
        #pragma unroll
        for (int it = 0; it < 8; ++it) {
            int i = blk * 8 + it;
            __half2 ui = us2[i];
            uint4 raw = ldgC_pol(Cp + (size_t)i * Nn, pol);
            const __half2* a = (const __half2*)&raw;
            __half2 e0 = h2exp2_fast(__hadd2(a[0], ui));
            __half2 e1 = h2exp2_fast(__hadd2(a[1], ui));
            __half2 e2 = h2exp2_fast(__hadd2(a[2], ui));
            __half2 e3 = h2exp2_fast(__hadd2(a[3], ui));
            h0 = __hadd2(h0, e0); h1 = __hadd2(h1, e1);
            h2 = __hadd2(h2, e2); h3 = __hadd2(h3, e3);
            if (FINAL) {
                float2 af, ef;
                af = __half22float2(a[0]); ef = __half22float2(e0);
                t[0].x = fmaf(af.x, ef.x, t[0].x); t[0].y = fmaf(af.y, ef.y, t[0].y);
                af = __half22float2(a[1]); ef = __half22float2(e1);
                t[1].x = fmaf(af.x, ef.x, t[1].x); t[1].y = fmaf(af.y, ef.y, t[1].y);
                af = __half22float2(a[2]); ef = __half22float2(e2);
                t[2].x = fmaf(af.x, ef.x, t[2].x); t[2].y = fmaf(af.y, ef.y, t[2].y);
                af = __half22float2(a[3]); ef = __half22float2(e3);
                t[3].x = fmaf(af.x, ef.x, t[3].x); t[3].y = fmaf(af.y, ef.y, t[3].y);
            }
        }
        float2 g;
        g = __half22float2(h0); f[0].x += g.x; f[0].y += g.y;
        g = __half22float2(h1); f[1].x += g.x; f[1].y += g.y;
        g = __half22float2(h2); f[2].x += g.x; f[2].y += g.y;
        g = __half22float2(h3); f[3].x += g.x; f[3].y += g.y;
    }
}

// partial col sums of 2^(a' + u_i*log2e)
template <bool FINAL>
__global__ void vpass_kernel() {
    __shared__ __half2 us2[VROWS];     // u_i*LOG2E duplicated in both halves
    int tid = threadIdx.x;             // 128
    int tile = blockIdx.x;             // 0..NTILE-1
    int chunk = blockIdx.y;            // 0..NCHUNK-1
    int i0 = chunk * VROWS;
    if (tid < VROWS)
        us2[tid] = __float2half2_rn(d_u[i0 + tid] * LOG2E);
    __syncthreads();

    int j = tile * VCOLS + tid * 8;
    const __half* Cp = d_C + (size_t)i0 * Nn + j;

    float2 f[4] = {make_float2(0.f, 0.f), make_float2(0.f, 0.f),
                   make_float2(0.f, 0.f), make_float2(0.f, 0.f)};
    float2 t[4] = {make_float2(0.f, 0.f), make_float2(0.f, 0.f),
                   make_float2(0.f, 0.f), make_float2(0.f, 0.f)};

    unsigned long long pol = (chunk < R_CHUNK) ? pol_last() : pol_first();
    vpass_body<FINAL>(Cp, us2, f, t, pol);

    *(float4*)&d_spart[chunk][j]     = make_float4(f[0].x, f[0].y, f[1].x, f[1].y);
    *(float4*)&d_spart[chunk][j + 4] = make_float4(f[2].x, f[2].y, f[3].x, f[3].y);
    if (FINAL) {
        *(float4*)&d_Tpart[chunk][j]     = make_float4(t[0].x, t[0].y, t[1].x, t[1].y);
        *(float4*)&d_Tpart[chunk][j + 4] = make_float4(t[2].x, t[2].y, t[3].x, t[3].y);
    }
}

// deterministic fixed-order merge of v partials
__global__ void vfinalize_kernel() {
    int j = blockIdx.x * blockDim.x + threadIdx.x;
    float s = 0.f;
    #pragma unroll
    for (int c = 0; c < NCHUNK; ++c) s += d_spart[c][j];
    float vp = d_v[j];
    float cc = (vp - LOG_AB) * LOG2E - BIAS;
    d_v[j] = vp - cc * LN2 - __logf(s);
}

// r_j = T_j/s_j in C units: ((sum a'e / sum e) - 12) / alpha
__global__ void rj_kernel() {
    int j = blockIdx.x * blockDim.x + threadIdx.x;
    float s = 0.f, t = 0.f;
    #pragma unroll
    for (int c = 0; c < NCHUNK; ++c) { s += d_spart[c][j]; t += d_Tpart[c][j]; }
    d_rj[j] = (t / s - BIAS) * d_invAlpha;
}

__global__ void result_kernel(float* __restrict__ out) {
    __shared__ float red[256];
    int tid = threadIdx.x;
    float s = 0.f;
    for (int j = tid; j < Nn; j += 256) s += d_rj[j];
    red[tid] = s;
    __syncthreads();
    for (int o = 128; o; o >>= 1) {
        if (tid < o) red[tid] += red[tid + o];
        __syncthreads();
    }
    if (tid == 0) out[0] = red[0] * (1.0f / Nn);
}

// ---------------------------------------------------------------------------
extern "C" void kernel_launch(void* const* d_in, const int* in_sizes, int n_in,
                              void* d_out, int out_size) {
    const float* XP = (const float*)d_in[0];
    const float* XQ = (const float*)d_in[1];
    float* out = (float*)d_out;

    norms_kernel<<<(2 * Nn) / 8, 256>>>(XP, XQ);
    init_kernel<<<Nn / 256, 256>>>();
    gemmC_kernel<<<dim3(Nn / 64, Nn / 64), 256>>>(XP, XQ);
    scale_kernel<<<1, 1>>>();
    rescale_kernel<<<(int)(((size_t)Nn * Nn) / 8 / 256), 256>>>();

    for (int t = 0; t < 20; ++t) {
        upass_kernel<<<Nn / 8, 256>>>();
        if (t < 19) {
            vpass_kernel<false><<<dim3(NTILE, NCHUNK), 128>>>();
            vfinalize_kernel<<<Nn / 256, 256>>>();
        } else {
            vpass_kernel<true><<<dim3(NTILE, NCHUNK), 128>>>();
            rj_kernel<<<Nn / 256, 256>>>();
            result_kernel<<<1, 256>>>(out);
        }
    }
}

// round 11
// speedup vs baseline: 1.2371x; 1.2371x over previous
#include <cuda_runtime.h>
#include <cuda_fp16.h>
#include <math.h>

#define Nn 8192
#define Dd 64
#define NCHUNK 128             // row chunks in v-pass
#define VROWS (Nn / NCHUNK)    // 64 rows per chunk
#define VCOLS 2048             // cols per tile (128 threads * 16)
#define NTILE (Nn / VCOLS)     // 4

#define LOG_AB (-9.010913347f)   // -ln(8192)
#define LOG2E  (1.4426950408889634f)
#define LN2    (0.6931471805599453f)
#define BIAS   (12.0f)
#define QAF    (0.1131525523f)    // LOG2E/(0.05*255): global constant
#define C0F    (12.0f + 1024.0f * QAF)   // 127.86821
#define CSF    (12.0f - (128.0f - 1024.0f * QAF))  // -0.1317865

// ---------------- device scratch ----------
__device__ __half d_C[(size_t)Nn * Nn];          // fp16 C (gemm output, read once)
__device__ unsigned char d_Q[(size_t)Nn * Nn];   // quantized a' source, 67 MB
__device__ float d_x2[Nn], d_y2[Nn];
__device__ float d_u[Nn], d_v[Nn];
__device__ float d_spart[NCHUNK][Nn];
__device__ float d_Tpart[NCHUNK][Nn];
__device__ float d_rj[Nn];
__device__ unsigned int d_cmax_bits;
__device__ float d_alpha;                  // negS*LOG2E  (negative)
__device__ float d_invAlpha;               // 1/alpha
__device__ float d_qscale;                 // 255/Cmax

__device__ __forceinline__ __half2 h2exp2_fast(__half2 x) {
    unsigned xi = *reinterpret_cast<unsigned*>(&x);
    unsigned ri;
    asm("ex2.approx.f16x2 %0, %1;" : "=r"(ri) : "r"(xi));
    return *reinterpret_cast<__half2*>(&ri);
}
__device__ __forceinline__ __half2 u32_as_h2(unsigned x) {
    return *reinterpret_cast<__half2*>(&x);
}

// ---------------- row norms ----------------
__global__ void norms_kernel(const float* __restrict__ XP,
                             const float* __restrict__ XQ) {
    int gwarp = (blockIdx.x * blockDim.x + threadIdx.x) >> 5;
    int lane = threadIdx.x & 31;
    const float* src;
    float* dst;
    int row;
    if (gwarp < Nn) { src = XP; dst = d_x2; row = gwarp; }
    else            { src = XQ; dst = d_y2; row = gwarp - Nn; }
    const float* r = src + (size_t)row * Dd;
    float a = r[lane];
    float b = r[lane + 32];
    float s = a * a + b * b;
    #pragma unroll
    for (int o = 16; o; o >>= 1) s += __shfl_xor_sync(0xffffffffu, s, o);
    if (lane == 0) dst[row] = s;
}

__global__ void init_kernel() {
    int j = blockIdx.x * blockDim.x + threadIdx.x;
    d_u[j] = 0.0f;
    d_v[j] = 0.0f;
    if (j == 0) d_cmax_bits = 0u;
}

// ---------------- C = max(x2 + y2 - 2 XP@XQ^T, 0) -> fp16, track fp32 max --
__global__ void gemmC_kernel(const float* __restrict__ XP,
                             const float* __restrict__ XQ) {
    __shared__ float As[Dd][64 + 4];
    __shared__ float Bs[Dd][64 + 4];
    int tid = threadIdx.x;             // 256 threads
    int m0 = blockIdx.y * 64;
    int n0 = blockIdx.x * 64;

    #pragma unroll
    for (int p = 0; p < 4; ++p) {
        int f = p * 256 + tid;
        int row = f >> 4;
        int c4 = f & 15;
        float4 a = *(const float4*)(XP + (size_t)(m0 + row) * Dd + c4 * 4);
        As[c4 * 4 + 0][row] = a.x; As[c4 * 4 + 1][row] = a.y;
        As[c4 * 4 + 2][row] = a.z; As[c4 * 4 + 3][row] = a.w;
        float4 b = *(const float4*)(XQ + (size_t)(n0 + row) * Dd + c4 * 4);
        Bs[c4 * 4 + 0][row] = b.x; Bs[c4 * 4 + 1][row] = b.y;
        Bs[c4 * 4 + 2][row] = b.z; Bs[c4 * 4 + 3][row] = b.w;
    }
    __syncthreads();

    int tx = tid & 15, ty = tid >> 4;
    float acc[4][4] = {};
    #pragma unroll
    for (int k = 0; k < Dd; ++k) {
        float4 a4 = *(const float4*)&As[k][ty * 4];
        float4 b4 = *(const float4*)&Bs[k][tx * 4];
        float a[4] = {a4.x, a4.y, a4.z, a4.w};
        float b[4] = {b4.x, b4.y, b4.z, b4.w};
        #pragma unroll
        for (int i = 0; i < 4; ++i)
            #pragma unroll
            for (int j = 0; j < 4; ++j)
                acc[i][j] = fmaf(a[i], b[j], acc[i][j]);
    }

    float cmaxl = 0.0f;
    #pragma unroll
    for (int i = 0; i < 4; ++i) {
        int m = m0 + ty * 4 + i;
        float xm = d_x2[m];
        float o[4];
        #pragma unroll
        for (int j = 0; j < 4; ++j) {
            int nj = n0 + tx * 4 + j;
            float c = fmaxf(xm + d_y2[nj] - 2.0f * acc[i][j], 0.0f);
            o[j] = c;
            cmaxl = fmaxf(cmaxl, c);
        }
        __half2* dst = (__half2*)(d_C + (size_t)m * Nn + n0 + tx * 4);
        dst[0] = __floats2half2_rn(o[0], o[1]);
        dst[1] = __floats2half2_rn(o[2], o[3]);
    }
    #pragma unroll
    for (int o = 16; o; o >>= 1)
        cmaxl = fmaxf(cmaxl, __shfl_xor_sync(0xffffffffu, cmaxl, o));
    if ((tid & 31) == 0)
        atomicMax(&d_cmax_bits, __float_as_uint(cmaxl));  // nonneg floats: bit order == value order
}

__global__ void scale_kernel() {
    float cmax = __uint_as_float(d_cmax_bits);
    float negS = -1.0f / (0.05f * cmax);
    float alpha = negS * LOG2E;
    d_alpha = alpha;
    d_invAlpha = 1.0f / alpha;
    d_qscale = 255.0f / cmax;
}

// quantize: q = round(C * 255/Cmax) -> uint8
__global__ void quantize_kernel() {
    float qs = d_qscale;
    size_t base = ((size_t)blockIdx.x * 256 + threadIdx.x) * 16;
    uint4 a = *(const uint4*)(d_C + base);       // 8 halves
    uint4 b = *(const uint4*)(d_C + base + 8);   // 8 halves
    const __half2* ha = (const __half2*)&a;
    const __half2* hb = (const __half2*)&b;
    unsigned bytes[4];
    #pragma unroll
    for (int w = 0; w < 4; ++w) {
        float2 f0 = __half22float2(w < 2 ? ha[w * 2]     : hb[(w - 2) * 2]);
        float2 f1 = __half22float2(w < 2 ? ha[w * 2 + 1] : hb[(w - 2) * 2 + 1]);
        unsigned q0 = __float2uint_rn(fminf(f0.x * qs, 255.0f));
        unsigned q1 = __float2uint_rn(fminf(f0.y * qs, 255.0f));
        unsigned q2 = __float2uint_rn(fminf(f1.x * qs, 255.0f));
        unsigned q3 = __float2uint_rn(fminf(f1.y * qs, 255.0f));
        bytes[w] = q0 | (q1 << 8) | (q2 << 16) | (q3 << 24);
    }
    *(uint4*)(d_Q + base) = make_uint4(bytes[0], bytes[1], bytes[2], bytes[3]);
}

// ---------------- u-pass: u_new = up - rc*ln2 - ln( sum_j 2^(a' + v_j*log2e) )
__global__ void upass_kernel() {
    __shared__ __half2 vs2[Nn / 2];    // vc_j = v_j*LOG2E + CSF, packed pairs
    int tid = threadIdx.x;             // 256
    #pragma unroll
    for (int p = 0; p < 8; ++p) {
        int idx = p * 256 + tid;       // float4 index
        float4 f = *(const float4*)&d_v[idx * 4];
        vs2[idx * 2]     = __floats2half2_rn(fmaf(f.x, LOG2E, CSF), fmaf(f.y, LOG2E, CSF));
        vs2[idx * 2 + 1] = __floats2half2_rn(fmaf(f.z, LOG2E, CSF), fmaf(f.w, LOG2E, CSF));
    }
    __syncthreads();

    int warp = tid >> 5, lane = tid & 31;
    int row = blockIdx.x * 8 + warp;
    float up = d_u[row];
    const unsigned char* Qrow = d_Q + (size_t)row * Nn;
    const __half2 qa2 = __float2half2_rn(-QAF);
    const __half2 c128 = __float2half2_rn(128.0f);

    float2 fs[8] = {};
    #pragma unroll
    for (int blk = 0; blk < 2; ++blk) {
        unsigned hacc[8] = {};         // half2 accumulators as u32
        #pragma unroll
        for (int it = 0; it < 8; ++it) {
            int j = (blk * 8 + it) * 512 + lane * 16;
            uint4 raw = *(const uint4*)(Qrow + j);
            uint4 v01 = *(const uint4*)&vs2[j >> 1];
            uint4 v23 = *(const uint4*)&vs2[(j >> 1) + 4];
            unsigned w[4] = {raw.x, raw.y, raw.z, raw.w};
            __half2 vcp[8];
            vcp[0] = u32_as_h2(v01.x); vcp[1] = u32_as_h2(v01.y);
            vcp[2] = u32_as_h2(v01.z); vcp[3] = u32_as_h2(v01.w);
            vcp[4] = u32_as_h2(v23.x); vcp[5] = u32_as_h2(v23.y);
            vcp[6] = u32_as_h2(v23.z); vcp[7] = u32_as_h2(v23.w);
            #pragma unroll
            for (int k = 0; k < 4; ++k) {
                __half2 hA = u32_as_h2(__byte_perm(w[k], 0x64646464u, 0x4140));
                __half2 hB = u32_as_h2(__byte_perm(w[k], 0x64646464u, 0x4342));
                __half2 aA = __hadd2(__hfma2(hA, qa2, c128), vcp[2 * k]);
                __half2 aB = __hadd2(__hfma2(hB, qa2, c128), vcp[2 * k + 1]);
                __half2 sA = __hadd2(u32_as_h2(hacc[2 * k]), h2exp2_fast(aA));
                __half2 sB = __hadd2(u32_as_h2(hacc[2 * k + 1]), h2exp2_fast(aB));
                hacc[2 * k] = *reinterpret_cast<unsigned*>(&sA);
                hacc[2 * k + 1] = *reinterpret_cast<unsigned*>(&sB);
            }
        }
        #pragma unroll
        for (int q = 0; q < 8; ++q) {
            float2 g = __half22float2(u32_as_h2(hacc[q]));
            fs[q].x += g.x; fs[q].y += g.y;
        }
    }
    float s = 0.f;
    #pragma unroll
    for (int q = 0; q < 8; ++q) s += fs[q].x + fs[q].y;
    #pragma unroll
    for (int o = 16; o; o >>= 1) s += __shfl_xor_sync(0xffffffffu, s, o);
    if (lane == 0) {
        float rc = (up - LOG_AB) * LOG2E - BIAS;
        d_u[row] = up - rc * LN2 - __logf(s);
    }
}

// ---------------- v-pass: partial col sums of 2^(a' + u_i*log2e) -----------
template <bool FINAL>
__global__ void vpass_kernel() {
    __shared__ __half2 us2[VROWS];     // uc_i = u_i*LOG2E + CSF, duplicated halves
    int tid = threadIdx.x;             // 128
    int tile = blockIdx.x;             // 0..NTILE-1
    int chunk = blockIdx.y;            // 0..NCHUNK-1
    int i0 = chunk * VROWS;
    if (tid < VROWS)
        us2[tid] = __float2half2_rn(fmaf(d_u[i0 + tid], LOG2E, CSF));
    __syncthreads();

    int j = tile * VCOLS + tid * 16;
    const unsigned char* Qp = d_Q + (size_t)i0 * Nn + j;
    const __half2 qa2 = __float2half2_rn(-QAF);
    const __half2 c128 = __float2half2_rn(128.0f);

    float2 fs[8] = {};
    float2 ts[8] = {};

    #pragma unroll
    for (int blk = 0; blk < VROWS / 8; ++blk) {
        unsigned hacc[8] = {};
        #pragma unroll
        for (int it = 0; it < 8; ++it) {
            int i = blk * 8 + it;
            __half2 uc = us2[i];
            uint4 raw = *(const uint4*)(Qp + (size_t)i * Nn);
            unsigned w[4] = {raw.x, raw.y, raw.z, raw.w};
            #pragma unroll
            for (int k = 0; k < 4; ++k) {
                __half2 hA = u32_as_h2(__byte_perm(w[k], 0x64646464u, 0x4140));
                __half2 hB = u32_as_h2(__byte_perm(w[k], 0x64646464u, 0x4342));
                __half2 aA = __hadd2(__hfma2(hA, qa2, c128), uc);
                __half2 aB = __hadd2(__hfma2(hB, qa2, c128), uc);
                __half2 eA = h2exp2_fast(aA);
                __half2 eB = h2exp2_fast(aB);
                __half2 sA = __hadd2(u32_as_h2(hacc[2 * k]), eA);
                __half2 sB = __hadd2(u32_as_h2(hacc[2 * k + 1]), eB);
                hacc[2 * k] = *reinterpret_cast<unsigned*>(&sA);
                hacc[2 * k + 1] = *reinterpret_cast<unsigned*>(&sB);
                if (FINAL) {
                    // a' = hf*(-QAF) + C0F  (log2-domain incl BIAS)
                    float2 hfA = __half22float2(hA);
                    float2 hfB = __half22float2(hB);
                    float2 efA = __half22float2(eA);
                    float2 efB = __half22float2(eB);
                    float apAx = fmaf(hfA.x, -QAF, C0F);
                    float apAy = fmaf(hfA.y, -QAF, C0F);
                    float apBx = fmaf(hfB.x, -QAF, C0F);
                    float apBy = fmaf(hfB.y, -QAF, C0F);
                    ts[2 * k].x = fmaf(apAx, efA.x, ts[2 * k].x);
                    ts[2 * k].y = fmaf(apAy, efA.y, ts[2 * k].y);
                    ts[2 * k + 1].x = fmaf(apBx, efB.x, ts[2 * k + 1].x);
                    ts[2 * k + 1].y = fmaf(apBy, efB.y, ts[2 * k + 1].y);
                }
            }
        }
        #pragma unroll
        for (int q = 0; q < 8; ++q) {
            float2 g = __half22float2(u32_as_h2(hacc[q]));
            fs[q].x += g.x; fs[q].y += g.y;
        }
    }
    #pragma unroll
    for (int q = 0; q < 4; ++q)
        *(float4*)&d_spart[chunk][j + q * 4] =
            make_float4(fs[2 * q].x, fs[2 * q].y, fs[2 * q + 1].x, fs[2 * q + 1].y);
    if (FINAL) {
        #pragma unroll
        for (int q = 0; q < 4; ++q)
            *(float4*)&d_Tpart[chunk][j + q * 4] =
                make_float4(ts[2 * q].x, ts[2 * q].y, ts[2 * q + 1].x, ts[2 * q + 1].y);
    }
}

// deterministic fixed-order merge of v partials
__global__ void vfinalize_kernel() {
    int j = blockIdx.x * blockDim.x + threadIdx.x;
    float s = 0.f;
    #pragma unroll
    for (int c = 0; c < NCHUNK; ++c) s += d_spart[c][j];
    float vp = d_v[j];
    float cc = (vp - LOG_AB) * LOG2E - BIAS;
    d_v[j] = vp - cc * LN2 - __logf(s);
}

// r_j = T_j/s_j in C units: ((sum a'e / sum e) - 12) / alpha
__global__ void rj_kernel() {
    int j = blockIdx.x * blockDim.x + threadIdx.x;
    float s = 0.f, t = 0.f;
    #pragma unroll
    for (int c = 0; c < NCHUNK; ++c) { s += d_spart[c][j]; t += d_Tpart[c][j]; }
    d_rj[j] = (t / s - BIAS) * d_invAlpha;
}

__global__ void result_kernel(float* __restrict__ out) {
    __shared__ float red[256];
    int tid = threadIdx.x;
    float s = 0.f;
    for (int j = tid; j < Nn; j += 256) s += d_rj[j];
    red[tid] = s;
    __syncthreads();
    for (int o = 128; o; o >>= 1) {
        if (tid < o) red[tid] += red[tid + o];
        __syncthreads();
    }
    if (tid == 0) out[0] = red[0] * (1.0f / Nn);
}

// ---------------------------------------------------------------------------
extern "C" void kernel_launch(void* const* d_in, const int* in_sizes, int n_in,
                              void* d_out, int out_size) {
    const float* XP = (const float*)d_in[0];
    const float* XQ = (const float*)d_in[1];
    float* out = (float*)d_out;

    norms_kernel<<<(2 * Nn) / 8, 256>>>(XP, XQ);
    init_kernel<<<Nn / 256, 256>>>();
    gemmC_kernel<<<dim3(Nn / 64, Nn / 64), 256>>>(XP, XQ);
    scale_kernel<<<1, 1>>>();
    quantize_kernel<<<(int)(((size_t)Nn * Nn) / 16 / 256), 256>>>();

    for (int t = 0; t < 20; ++t) {
        upass_kernel<<<Nn / 8, 256>>>();
        if (t < 19) {
            vpass_kernel<false><<<dim3(NTILE, NCHUNK), 128>>>();
            vfinalize_kernel<<<Nn / 256, 256>>>();
        } else {
            vpass_kernel<true><<<dim3(NTILE, NCHUNK), 128>>>();
            rj_kernel<<<Nn / 256, 256>>>();
            result_kernel<<<1, 256>>>(out);
        }
    }
}